// round 13
// baseline (speedup 1.0000x reference)
#include <cuda_runtime.h>
#include <cstdint>

#define SQ 2048
#define DM 4096
#define NH 32
#define HD 128

// Scratch (allocation-free rule: __device__ globals).
__device__ float g_q[(size_t)SQ * DM];
__device__ float g_k[(size_t)SQ * DM];
__device__ float g_v[(size_t)SQ * DM];
__device__ float g_att[(size_t)SQ * DM];
__device__ float g_xc[(size_t)SQ * DM];     // tf32(x)
__device__ float g_wt0[(size_t)DM * DM];    // tf32(wq^T)
__device__ float g_wt1[(size_t)DM * DM];    // tf32(wk^T)
__device__ float g_wt2[(size_t)DM * DM];    // tf32(wv^T)
__device__ float g_wt3[(size_t)DM * DM];    // tf32(wo^T)

// ============================================================================
// Helpers (baseline PTX only — harness compiles at plain sm_103)
// ============================================================================
__device__ __forceinline__ float to_tf32(float x) {
    uint32_t u;
    asm("cvt.rna.tf32.f32 %0, %1;" : "=r"(u) : "f"(x));
    return __uint_as_float(u);
}

__device__ __forceinline__ uint32_t smem_u32(const void* p) {
    uint32_t a;
    asm("{ .reg .u64 t; cvta.to.shared.u64 t, %1; cvt.u32.u64 %0, t; }"
        : "=r"(a) : "l"(p));
    return a;
}

__device__ __forceinline__ void cp16(uint32_t dst, const void* src) {
    asm volatile(
        "{ .reg .u64 gp; cvta.to.global.u64 gp, %1;"
        "  cp.async.cg.shared.global [%0], [gp], 16; }"
        :: "r"(dst), "l"(src) : "memory");
}
#define CP_COMMIT() asm volatile("cp.async.commit_group;" ::: "memory")
#define CP_WAIT1()  asm volatile("cp.async.wait_group 1;" ::: "memory")

// ldmatrix x4 on tf32 data: four 8x4 b32 matrices; reg r of thread t holds
// element (t/4, t%4) of matrix r; matrix r's rows are addressed by threads 8r..8r+7.
__device__ __forceinline__ void ldsm4(uint32_t* r, uint32_t addr) {
    asm volatile("ldmatrix.sync.aligned.m8n8.x4.shared.b16 {%0,%1,%2,%3}, [%4];"
        : "=r"(r[0]), "=r"(r[1]), "=r"(r[2]), "=r"(r[3]) : "r"(addr));
}

__device__ __forceinline__ void mma8(float* d, const uint32_t* a, const uint32_t* b) {
    asm volatile(
        "mma.sync.aligned.m16n8k8.row.col.f32.tf32.tf32.f32 "
        "{%0,%1,%2,%3}, {%4,%5,%6,%7}, {%8,%9}, {%0,%1,%2,%3};"
        : "+f"(d[0]), "+f"(d[1]), "+f"(d[2]), "+f"(d[3])
        : "r"(a[0]), "r"(a[1]), "r"(a[2]), "r"(a[3]), "r"(b[0]), "r"(b[1]));
}

// ============================================================================
// Pre-pass kernels
// ============================================================================
__global__ void conv_tf32(const float4* __restrict__ s, float4* __restrict__ d) {
    int i = blockIdx.x * blockDim.x + threadIdx.x;
    float4 v = s[i];
    v.x = to_tf32(v.x); v.y = to_tf32(v.y);
    v.z = to_tf32(v.z); v.w = to_tf32(v.w);
    d[i] = v;
}

// dst[n][k] = tf32(src[k][n]), DM x DM
__global__ void transpose_tf32(const float* __restrict__ src, float* __restrict__ dst) {
    __shared__ float t[32][33];
    int x  = blockIdx.x * 32 + threadIdx.x;   // n in src
    int y0 = blockIdx.y * 32;                 // k base
#pragma unroll
    for (int i = 0; i < 32; i += 8)
        t[threadIdx.y + i][threadIdx.x] =
            to_tf32(src[(size_t)(y0 + threadIdx.y + i) * DM + x]);
    __syncthreads();
    int xo = blockIdx.y * 32 + threadIdx.x;   // k in dst
    int yo = blockIdx.x * 32;                 // n base
#pragma unroll
    for (int i = 0; i < 32; i += 8)
        dst[(size_t)(yo + threadIdx.y + i) * DM + xo] = t[threadIdx.x][threadIdx.y + i];
}

// ============================================================================
// TF32 GEMM via ldmatrix: C[2048,4096] = A[2048,4096] @ Bt^T, A and Bt both
// row-major [row][k], pre-converted to tf32. CTA tile 128x128, K-stage 32,
// 3-stage cp.async, 2 CTAs/SM, ONE barrier per k-iteration:
//   [wait stage i][sync][issue stage i+2][compute stage i]
// The barrier proves all threads finished reading slot (i-1)%3 in iter i-1,
// so issuing stage i+2 into that slot after the barrier is race-free.
// ============================================================================
#define NSTAGE 3
#define RST 36
#define TILEB (128 * RST * 4)               // 18432 B per operand tile
#define STAGEB (2 * TILEB)                  // 36864 B
#define GEMM_DSMEM (NSTAGE * STAGEB)        // 110592 B
#define GNIT (DM / 32)                      // 128

template <bool ROPE, bool OTF32>
__global__ void __launch_bounds__(256, 2) gemm_lm(
    const float* __restrict__ A, const float* __restrict__ Bt, float* __restrict__ C,
    const float* __restrict__ fc, const float* __restrict__ fs)
{
    extern __shared__ float sm[];
    const uint32_t smb = smem_u32(sm);

    const int tid  = threadIdx.x;
    const int lane = tid & 31;
    const int warp = tid >> 5;
    const int bm = blockIdx.y * 128;
    const int bn = blockIdx.x * 128;
    const int wm = (warp & 3) * 32;     // 4 warps along M
    const int wn = (warp >> 2) * 64;    // 2 warps along N
    const int g  = lane >> 2;
    const int t4 = lane & 3;

    // staging jobs: 4 x 16B for each operand per thread per stage
    int row[4], chk[4];
#pragma unroll
    for (int it = 0; it < 4; ++it) {
        int f = tid + it * 256;
        row[it] = f >> 3;
        chk[it] = f & 7;
    }

    // ldmatrix per-thread source rows/cols
    const int arow = ((lane >> 3) & 1) * 8 + (lane & 7);
    const uint32_t acol16 = ((lane >> 4) & 1) * 16;
    const uint32_t abase = (uint32_t)(wm + arow) * 144 + acol16;
    const int brow = ((lane >> 4) & 1) * 8 + (lane & 7);
    const uint32_t bcol16 = ((lane >> 3) & 1) * 16;
    const uint32_t bbase = (uint32_t)(wn + brow) * 144 + bcol16;

    float acc[2][8][4];
#pragma unroll
    for (int a = 0; a < 2; a++)
#pragma unroll
        for (int b = 0; b < 8; b++)
#pragma unroll
            for (int c = 0; c < 4; c++) acc[a][b][c] = 0.f;

    // ---- prologue: stages 0,1 in flight (2 groups)
#pragma unroll
    for (int p = 0; p < 2; ++p) {
        uint32_t sa = smb + (uint32_t)(p * STAGEB);
        int k0 = p * 32;
#pragma unroll
        for (int it = 0; it < 4; ++it) {
            uint32_t doff = (uint32_t)(row[it] * 144 + chk[it] * 16);
            cp16(sa + doff,         A  + (size_t)(bm + row[it]) * DM + k0 + chk[it] * 4);
            cp16(sa + TILEB + doff, Bt + (size_t)(bn + row[it]) * DM + k0 + chk[it] * 4);
        }
        CP_COMMIT();
    }

    for (int i = 0; i < GNIT; ++i) {
        CP_WAIT1();            // stage i resident (this thread's copies)
        __syncthreads();       // ... everyone's; also: slot (i-1)%3 fully consumed

        // ---- issue stage i+2 into slot (i-1)%3 (safe after the barrier)
        if (i + 2 < GNIT) {
            uint32_t sa = smb + (uint32_t)(((i + 2) % NSTAGE) * STAGEB);
            int k0 = (i + 2) * 32;
#pragma unroll
            for (int it = 0; it < 4; ++it) {
                uint32_t doff = (uint32_t)(row[it] * 144 + chk[it] * 16);
                cp16(sa + doff,         A  + (size_t)(bm + row[it]) * DM + k0 + chk[it] * 4);
                cp16(sa + TILEB + doff, Bt + (size_t)(bn + row[it]) * DM + k0 + chk[it] * 4);
            }
        }
        CP_COMMIT();           // unconditional: keeps group accounting uniform

        const uint32_t sa = smb + (uint32_t)((i % NSTAGE) * STAGEB);
        const uint32_t sb = sa + TILEB;

#pragma unroll
        for (int kk = 0; kk < 32; kk += 8) {
            uint32_t af[2][4];
            ldsm4(af[0], sa + abase + kk * 4);
            ldsm4(af[1], sa + abase + 16 * 144 + kk * 4);
            uint32_t bq[4][4];
#pragma unroll
            for (int p = 0; p < 4; ++p)
                ldsm4(bq[p], sb + bbase + (uint32_t)(p * 16 * 144) + kk * 4);
#pragma unroll
            for (int mt = 0; mt < 2; ++mt)
#pragma unroll
                for (int nt = 0; nt < 8; ++nt)
                    mma8(acc[mt][nt], af[mt], &bq[nt >> 1][(nt & 1) * 2]);
        }
    }

    // ---- epilogue (optional fused RoPE; optional tf32-rounded output)
#pragma unroll
    for (int mt = 0; mt < 2; ++mt)
#pragma unroll
        for (int nt = 0; nt < 8; ++nt) {
            int r = bm + wm + mt * 16 + g;
            int c = bn + wn + nt * 8 + (t4 << 1);
            float x0 = acc[mt][nt][0];
            float x1 = acc[mt][nt][1];
            float x2 = acc[mt][nt][2];
            float x3 = acc[mt][nt][3];
            if (ROPE) {
                int fi = (c & (HD - 1)) >> 1;
                float c0 = fc[(size_t)r * (HD / 2) + fi];
                float s0 = fs[(size_t)r * (HD / 2) + fi];
                float c1 = fc[(size_t)(r + 8) * (HD / 2) + fi];
                float s1 = fs[(size_t)(r + 8) * (HD / 2) + fi];
                float y0 = x0 * c0 - x1 * s0;
                float y1 = x0 * s0 + x1 * c0;
                float y2 = x2 * c1 - x3 * s1;
                float y3 = x2 * s1 + x3 * c1;
                x0 = y0; x1 = y1; x2 = y2; x3 = y3;
            }
            if (OTF32) {
                x0 = to_tf32(x0); x1 = to_tf32(x1);
                x2 = to_tf32(x2); x3 = to_tf32(x3);
            }
            float2 v;
            v.x = x0; v.y = x1;
            *reinterpret_cast<float2*>(C + (size_t)r * DM + c) = v;
            v.x = x2; v.y = x3;
            *reinterpret_cast<float2*>(C + (size_t)(r + 8) * DM + c) = v;
        }
}

// ============================================================================
// Fused flash attention (causal), tf32 mma.sync (unchanged, known-good).
// ============================================================================
#define QST 132
#define VST 136
#define QS_OFF 0
#define KS_OFF (128 * QST)
#define VS_OFF (KS_OFF + 128 * QST)
#define ATN_SMEM ((VS_OFF + 128 * VST) * (int)sizeof(float))   // 204800 B

__global__ void __launch_bounds__(256, 1) attn_fused(
    const float* __restrict__ Q, const float* __restrict__ K,
    const float* __restrict__ V, float* __restrict__ Oa)
{
    extern __shared__ float smem[];
    const uint32_t smb = smem_u32(smem);

    const int h  = blockIdx.y;
    const int i0 = (SQ / 128 - 1 - (int)blockIdx.x) * 128;  // heavy tiles first
    const int tid  = threadIdx.x;
    const int lane = tid & 31;
    const int warp = tid >> 5;
    const int g  = lane >> 2;
    const int t4 = lane & 3;
    const int w16 = warp * 16;
    const float scale = 0.08838834764831845f;   // 1/sqrt(128)

    const int qrow = ((lane >> 3) & 1) * 8 + (lane & 7);
    const uint32_t qaddr = smb + (uint32_t)(QS_OFF + (w16 + qrow) * QST) * 4
                         + ((lane >> 4) & 1) * 16;
    const int krow = ((lane >> 4) & 1) * 8 + (lane & 7);
    const uint32_t kaddr = smb + (uint32_t)(KS_OFF + krow * QST) * 4
                         + ((lane >> 3) & 1) * 16;

    // ---- load Q tile once (natural layout, STS.128)
#pragma unroll
    for (int it = 0; it < 16; ++it) {
        int f   = tid + it * 256;
        int r   = f >> 5;
        int c4  = (f & 31) << 2;
        float4 v4 = *reinterpret_cast<const float4*>(
            Q + (size_t)(i0 + r) * DM + h * HD + c4);
        *reinterpret_cast<float4*>(&smem[QS_OFF + r * QST + c4]) = v4;
    }

    float o[16][4];
#pragma unroll
    for (int n = 0; n < 16; ++n)
#pragma unroll
        for (int c = 0; c < 4; ++c) o[n][c] = 0.f;
    float m0 = -1e30f, m1 = -1e30f, l0 = 0.f, l1 = 0.f;

    const int r0g = i0 + w16 + g;
    const unsigned FULL = 0xffffffffu;

    for (int j0 = 0; j0 <= i0; j0 += 128) {
        __syncthreads();
#pragma unroll
        for (int it = 0; it < 16; ++it) {
            int f   = tid + it * 256;
            int r   = f >> 5;
            int c4  = (f & 31) << 2;
            float4 kv = *reinterpret_cast<const float4*>(
                K + (size_t)(j0 + r) * DM + h * HD + c4);
            *reinterpret_cast<float4*>(&smem[KS_OFF + r * QST + c4]) = kv;
            float4 vv = *reinterpret_cast<const float4*>(
                V + (size_t)(j0 + r) * DM + h * HD + c4);
            *reinterpret_cast<float4*>(&smem[VS_OFF + r * VST + c4]) = vv;
        }
        __syncthreads();

        float s[16][4];
#pragma unroll
        for (int n = 0; n < 16; ++n)
#pragma unroll
            for (int c = 0; c < 4; ++c) s[n][c] = 0.f;

#pragma unroll
        for (int kk = 0; kk < 128; kk += 8) {
            uint32_t af[4];
            ldsm4(af, qaddr + kk * 4);
            uint32_t bq[8][4];
#pragma unroll
            for (int p = 0; p < 8; ++p)
                ldsm4(bq[p], kaddr + (uint32_t)(p * 16 * QST) * 4 + kk * 4);
#pragma unroll
            for (int n = 0; n < 16; ++n)
                mma8(s[n], af, &bq[n >> 1][(n & 1) * 2]);
        }

        const bool diag = (j0 == i0);
#pragma unroll
        for (int n = 0; n < 16; ++n) {
            int c = j0 + n * 8 + (t4 << 1);
            s[n][0] *= scale; s[n][1] *= scale;
            s[n][2] *= scale; s[n][3] *= scale;
            if (diag) {
                if (c     > r0g)     s[n][0] = -1e30f;
                if (c + 1 > r0g)     s[n][1] = -1e30f;
                if (c     > r0g + 8) s[n][2] = -1e30f;
                if (c + 1 > r0g + 8) s[n][3] = -1e30f;
            }
        }

        float tm0 = -1e30f, tm1 = -1e30f;
#pragma unroll
        for (int n = 0; n < 16; ++n) {
            tm0 = fmaxf(tm0, fmaxf(s[n][0], s[n][1]));
            tm1 = fmaxf(tm1, fmaxf(s[n][2], s[n][3]));
        }
        tm0 = fmaxf(tm0, __shfl_xor_sync(FULL, tm0, 1));
        tm0 = fmaxf(tm0, __shfl_xor_sync(FULL, tm0, 2));
        tm1 = fmaxf(tm1, __shfl_xor_sync(FULL, tm1, 1));
        tm1 = fmaxf(tm1, __shfl_xor_sync(FULL, tm1, 2));
        float nm0 = fmaxf(m0, tm0), nm1 = fmaxf(m1, tm1);
        float a0 = __expf(m0 - nm0), a1 = __expf(m1 - nm1);
        m0 = nm0; m1 = nm1;

        float ts0 = 0.f, ts1 = 0.f;
#pragma unroll
        for (int n = 0; n < 16; ++n) {
            s[n][0] = __expf(s[n][0] - m0);
            s[n][1] = __expf(s[n][1] - m0);
            s[n][2] = __expf(s[n][2] - m1);
            s[n][3] = __expf(s[n][3] - m1);
            ts0 += s[n][0] + s[n][1];
            ts1 += s[n][2] + s[n][3];
        }
        ts0 += __shfl_xor_sync(FULL, ts0, 1);
        ts0 += __shfl_xor_sync(FULL, ts0, 2);
        ts1 += __shfl_xor_sync(FULL, ts1, 1);
        ts1 += __shfl_xor_sync(FULL, ts1, 2);
        l0 = l0 * a0 + ts0;
        l1 = l1 * a1 + ts1;
#pragma unroll
        for (int n = 0; n < 16; ++n) {
            o[n][0] *= a0; o[n][1] *= a0;
            o[n][2] *= a1; o[n][3] *= a1;
        }

        const int bse = lane & 28;
        const int sl0 = bse + (t4 >> 1);
        const int sl1 = sl0 + 2;
        const bool odd = (t4 & 1);
#pragma unroll
        for (int n = 0; n < 16; ++n) {
            float pa = __shfl_sync(FULL, s[n][0], sl0);
            float pb = __shfl_sync(FULL, s[n][1], sl0);
            float pc = __shfl_sync(FULL, s[n][2], sl0);
            float pd = __shfl_sync(FULL, s[n][3], sl0);
            float pe = __shfl_sync(FULL, s[n][0], sl1);
            float pf = __shfl_sync(FULL, s[n][1], sl1);
            float pg = __shfl_sync(FULL, s[n][2], sl1);
            float ph = __shfl_sync(FULL, s[n][3], sl1);
            uint32_t af[4];
            af[0] = __float_as_uint(to_tf32(odd ? pb : pa));
            af[1] = __float_as_uint(to_tf32(odd ? pd : pc));
            af[2] = __float_as_uint(to_tf32(odd ? pf : pe));
            af[3] = __float_as_uint(to_tf32(odd ? ph : pg));
            int kk = n * 8;
#pragma unroll
            for (int nn = 0; nn < 16; ++nn) {
                uint32_t bf[2];
                bf[0] = __float_as_uint(smem[VS_OFF + (kk + t4) * VST + nn * 8 + g]);
                bf[1] = __float_as_uint(smem[VS_OFF + (kk + t4 + 4) * VST + nn * 8 + g]);
                mma8(o[nn], af, bf);
            }
        }
    }

    // ---- normalize + write tf32-rounded (feeds output projection pre-converted)
    float inv0 = 1.f / l0, inv1 = 1.f / l1;
#pragma unroll
    for (int nn = 0; nn < 16; ++nn) {
        int c = h * HD + nn * 8 + (t4 << 1);
        float2 v;
        v.x = to_tf32(o[nn][0] * inv0); v.y = to_tf32(o[nn][1] * inv0);
        *reinterpret_cast<float2*>(Oa + (size_t)r0g * DM + c) = v;
        v.x = to_tf32(o[nn][2] * inv1); v.y = to_tf32(o[nn][3] * inv1);
        *reinterpret_cast<float2*>(Oa + (size_t)(r0g + 8) * DM + c) = v;
    }
}

extern "C" void kernel_launch(void* const* d_in, const int* in_sizes, int n_in,
                              void* d_out, int out_size)
{
    (void)in_sizes; (void)n_in; (void)out_size;
    const float* x  = (const float*)d_in[0];
    const float* wq = (const float*)d_in[1];
    const float* wk = (const float*)d_in[2];
    const float* wv = (const float*)d_in[3];
    const float* wo = (const float*)d_in[4];
    const float* fc = (const float*)d_in[5];
    const float* fs = (const float*)d_in[6];
    // d_in[7] (mask) handled analytically as causal; d_in[8] (start_pos) == 0.
    float* out = (float*)d_out;

    float *q, *k, *v, *att, *xc, *wt0, *wt1, *wt2, *wt3;
    cudaGetSymbolAddress((void**)&q,   g_q);
    cudaGetSymbolAddress((void**)&k,   g_k);
    cudaGetSymbolAddress((void**)&v,   g_v);
    cudaGetSymbolAddress((void**)&att, g_att);
    cudaGetSymbolAddress((void**)&xc,  g_xc);
    cudaGetSymbolAddress((void**)&wt0, g_wt0);
    cudaGetSymbolAddress((void**)&wt1, g_wt1);
    cudaGetSymbolAddress((void**)&wt2, g_wt2);
    cudaGetSymbolAddress((void**)&wt3, g_wt3);

    cudaFuncSetAttribute(gemm_lm<true, true>,
                         cudaFuncAttributeMaxDynamicSharedMemorySize, GEMM_DSMEM);
    cudaFuncSetAttribute(gemm_lm<false, true>,
                         cudaFuncAttributeMaxDynamicSharedMemorySize, GEMM_DSMEM);
    cudaFuncSetAttribute(gemm_lm<false, false>,
                         cudaFuncAttributeMaxDynamicSharedMemorySize, GEMM_DSMEM);
    cudaFuncSetAttribute(attn_fused,
                         cudaFuncAttributeMaxDynamicSharedMemorySize, ATN_SMEM);

    const dim3 blk(256);
    const dim3 gproj(DM / 128, SQ / 128, 1);    // (32, 16)
    const dim3 gtr(DM / 32, DM / 32, 1);        // (128, 128)
    const dim3 btr(32, 8, 1);

    // ---- pre-passes first (launches #0..#4) so launch #5 = gemmQ gets profiled
    conv_tf32<<<(SQ * DM / 4) / 256, 256>>>((const float4*)x, (float4*)xc);   // 0
    transpose_tf32<<<gtr, btr>>>(wq, wt0);                                    // 1
    transpose_tf32<<<gtr, btr>>>(wk, wt1);                                    // 2
    transpose_tf32<<<gtr, btr>>>(wv, wt2);                                    // 3
    transpose_tf32<<<gtr, btr>>>(wo, wt3);                                    // 4

    // ---- projections (RoPE fused into Q/K epilogues)
    gemm_lm<true, true ><<<gproj, blk, GEMM_DSMEM>>>(xc, wt0, q, fc, fs);     // 5 (profiled)
    gemm_lm<true, true ><<<gproj, blk, GEMM_DSMEM>>>(xc, wt1, k, fc, fs);     // 6
    gemm_lm<false, true><<<gproj, blk, GEMM_DSMEM>>>(xc, wt2, v, nullptr, nullptr); // 7

    // ---- fused causal attention (writes tf32-rounded att)
    attn_fused<<<dim3(SQ / 128, NH), blk, ATN_SMEM>>>(q, k, v, att);          // 8

    // ---- output projection (full-precision fp32 output)
    gemm_lm<false, false><<<gproj, blk, GEMM_DSMEM>>>(att, wt3, out, nullptr, nullptr); // 9
}